// round 3
// baseline (speedup 1.0000x reference)
#include <cuda_runtime.h>

// ParallelVarPatchEmbed: out[b,v,hw,e] = sum_{p,q} x[b,v,h*16+p,w*16+q] * W[in_vars[v],e,p,q] + bias[in_vars[v],e]
// Per (b,v): GEMM [1024 x 256] @ [256 x 128].
// Tiling: block = (b, v, 4 patch rows) -> M_tile=128 patches, N=128, K in chunks of 32.
// 256 threads, 8x8 outputs each, accumulated as f32x2 pairs (packed FFMA2).

__device__ __forceinline__ void fma2(unsigned long long& d, unsigned long long a, unsigned long long b) {
    asm("fma.rn.f32x2 %0, %1, %2, %0;" : "+l"(d) : "l"(a), "l"(b));
}
__device__ __forceinline__ unsigned long long dup2(float a) {
    unsigned long long r;
    asm("mov.b64 %0, {%1, %1};" : "=l"(r) : "f"(a));
    return r;
}

// Robust in_vars decode: JAX default config demotes int64 -> int32, so the
// buffer may be either. Read only the first 32 bytes (safe under both):
// int64 values < MAX_VARS=10 have zero high words at odd int32 positions.
__device__ __forceinline__ int get_var(const int* __restrict__ p32, int v) {
    bool is64 = ((p32[1] | p32[3] | p32[5] | p32[7]) == 0);
    return is64 ? p32[2 * v] : p32[v];
}

__global__ __launch_bounds__(256, 2)
void pve_kernel(const float* __restrict__ x,
                const int* __restrict__ in_vars,
                const float* __restrict__ w,
                const float* __restrict__ bias,
                float* __restrict__ out)
{
    constexpr int V = 8, Wd = 512, E = 128;

    __shared__ float As[32][132];   // [k within chunk][m patch]  (+4 pad)
    __shared__ float Bs[32][132];   // [k within chunk][e]

    const int rg = blockIdx.x;      // 0..7  : group of 4 patch rows
    const int v  = blockIdx.y;      // 0..7
    const int b  = blockIdx.z;      // 0..15
    const int var = get_var(in_vars, v);

    const int tid = threadIdx.x;
    const int tr  = tid >> 4;       // 0..15 -> patches m = tr*8 .. tr*8+7
    const int tc  = tid & 15;       // 0..15 -> embeds  e = tc*8 .. tc*8+7

    // x rows rg*64 .. rg*64+63 of image (b,v)
    const float* xbase = x + ((size_t)(b * V + v)) * (512 * 512) + (size_t)rg * 64 * Wd;
    const float* wbase = w + (size_t)var * (E * 256);   // [E][256] row-major

    unsigned long long acc[8][4];
    #pragma unroll
    for (int i = 0; i < 8; i++)
        #pragma unroll
        for (int j = 0; j < 4; j++) acc[i][j] = 0ULL;

    for (int kc = 0; kc < 8; kc++) {
        __syncthreads();
        // ---- load A chunk: 8 contiguous image rows of 512 floats (coalesced) ----
        #pragma unroll
        for (int i = 0; i < 16; i++) {
            int idx = tid + 256 * i;          // 0..4095
            int rl  = idx >> 9;               // 0..7
            int col = idx & 511;              // 0..511
            int pr  = rl >> 1;                // patch row 0..3
            int dp  = rl & 1;                 // p within chunk
            int q   = col & 15;
            int pc  = col >> 4;
            As[dp * 16 + q][pr * 32 + pc] = xbase[(pr * 16 + kc * 2 + dp) * Wd + col];
        }
        // ---- load B chunk: 32 k-values for all 128 e (coalesced over k fast dim) ----
        #pragma unroll
        for (int i = 0; i < 16; i++) {
            int idx = tid + 256 * i;          // 0..4095
            int e   = idx >> 5;               // 0..127
            int kk  = idx & 31;
            Bs[kk][e] = wbase[e * 256 + kc * 32 + kk];
        }
        __syncthreads();

        // ---- compute: 32 k-steps, 8x8 per thread via f32x2 ----
        #pragma unroll 8
        for (int kk = 0; kk < 32; kk++) {
            float4 a0 = *reinterpret_cast<const float4*>(&As[kk][tr * 8]);
            float4 a1 = *reinterpret_cast<const float4*>(&As[kk][tr * 8 + 4]);
            float4 b0 = *reinterpret_cast<const float4*>(&Bs[kk][tc * 8]);
            float4 b1 = *reinterpret_cast<const float4*>(&Bs[kk][tc * 8 + 4]);

            unsigned long long bp[4];
            bp[0] = *reinterpret_cast<unsigned long long*>(&b0.x);
            bp[1] = *reinterpret_cast<unsigned long long*>(&b0.z);
            bp[2] = *reinterpret_cast<unsigned long long*>(&b1.x);
            bp[3] = *reinterpret_cast<unsigned long long*>(&b1.z);

            unsigned long long ap[8];
            ap[0] = dup2(a0.x); ap[1] = dup2(a0.y); ap[2] = dup2(a0.z); ap[3] = dup2(a0.w);
            ap[4] = dup2(a1.x); ap[5] = dup2(a1.y); ap[6] = dup2(a1.z); ap[7] = dup2(a1.w);

            #pragma unroll
            for (int i = 0; i < 8; i++)
                #pragma unroll
                for (int j = 0; j < 4; j++)
                    fma2(acc[i][j], ap[i], bp[j]);
        }
    }

    // ---- epilogue: add bias, store ----
    float bv[8];
    const float* bb = bias + var * E + tc * 8;
    #pragma unroll
    for (int j = 0; j < 8; j++) bv[j] = __ldg(&bb[j]);

    // out index: ((b*V+v)*1024 + rg*128 + m) * 128 + e
    float* obase = out + (((size_t)(b * V + v) * 1024) + (size_t)rg * 128) * 128;
    #pragma unroll
    for (int i = 0; i < 8; i++) {
        int m = tr * 8 + i;
        float* op = obase + (size_t)m * 128 + tc * 8;
        float2 p0 = *reinterpret_cast<float2*>(&acc[i][0]);
        float2 p1 = *reinterpret_cast<float2*>(&acc[i][1]);
        float2 p2 = *reinterpret_cast<float2*>(&acc[i][2]);
        float2 p3 = *reinterpret_cast<float2*>(&acc[i][3]);
        float4 o0 = make_float4(p0.x + bv[0], p0.y + bv[1], p1.x + bv[2], p1.y + bv[3]);
        float4 o1 = make_float4(p2.x + bv[4], p2.y + bv[5], p3.x + bv[6], p3.y + bv[7]);
        *reinterpret_cast<float4*>(op)     = o0;
        *reinterpret_cast<float4*>(op + 4) = o1;
    }
}

extern "C" void kernel_launch(void* const* d_in, const int* in_sizes, int n_in,
                              void* d_out, int out_size)
{
    const float* x       = (const float*)d_in[0];
    const int*   in_vars = (const int*)d_in[1];
    const float* w       = (const float*)d_in[2];
    const float* bias    = (const float*)d_in[3];
    float*       out     = (float*)d_out;

    dim3 grid(8, 8, 16);   // (row groups, V, B) -> 1024 blocks
    pve_kernel<<<grid, 256>>>(x, in_vars, w, bias, out);
}

// round 5
// speedup vs baseline: 2.3004x; 2.3004x over previous
#include <cuda_runtime.h>
#include <cstdint>

// ParallelVarPatchEmbed via legacy mma.sync m16n8k8 TF32 (plain sm_103 target —
// tcgen05 is unavailable because the harness compiles through compute_103 PTX).
// Per CTA: D[128 x 128] = A[128 x 256] @ B^T + bias, A = patches of x, B = W[var].
// 8 warps in 4x2: warp tile m32 x n64. K chunked by 64, register-staged double buffer.

static constexpr int THREADS = 256;

// SMEM (floats): bias[128] | A bufs 2 x 8704 | B bufs 2 x 8704
static constexpr int BIAS_OFF = 0;
static constexpr int A_OFF    = 128;
static constexpr int B_OFF    = 128 + 2 * 8704;
static constexpr int SMEM_FLOATS = 128 + 4 * 8704;               // 34944
static constexpr int SMEM_BYTES  = SMEM_FLOATS * 4;              // 139776

__device__ __forceinline__ uint32_t f2tf32(float f) {
    uint32_t r;
    asm("cvt.rna.tf32.f32 %0, %1;" : "=r"(r) : "f"(f));
    return r;
}
__device__ __forceinline__ uint4 cvt4(float4 v) {
    uint4 r;
    r.x = f2tf32(v.x); r.y = f2tf32(v.y); r.z = f2tf32(v.z); r.w = f2tf32(v.w);
    return r;
}
__device__ __forceinline__ void mma8(float* c, const uint32_t* a, uint32_t b0, uint32_t b1) {
    asm volatile(
        "mma.sync.aligned.m16n8k8.row.col.f32.tf32.tf32.f32 "
        "{%0,%1,%2,%3}, {%4,%5,%6,%7}, {%8,%9}, {%0,%1,%2,%3};"
        : "+f"(c[0]), "+f"(c[1]), "+f"(c[2]), "+f"(c[3])
        : "r"(a[0]), "r"(a[1]), "r"(a[2]), "r"(a[3]), "r"(b0), "r"(b1));
}

// JAX demotes int64->int32 silently; detect layout from first 32 bytes.
__device__ __forceinline__ int get_var(const int* __restrict__ p32, int v) {
    bool is64 = ((p32[1] | p32[3] | p32[5] | p32[7]) == 0);
    return is64 ? p32[2 * v] : p32[v];
}

__global__ __launch_bounds__(THREADS, 1)
void pve_mma_kernel(const float* __restrict__ x,
                    const int* __restrict__ in_vars,
                    const float* __restrict__ w,
                    const float* __restrict__ bias,
                    float* __restrict__ out)
{
    extern __shared__ float smf[];

    const int tid  = threadIdx.x;
    const int wid  = tid >> 5;
    const int lane = tid & 31;
    const int qrow = lane >> 2;     // 0..7
    const int qcol = lane & 3;      // 0..3
    const int m0   = (wid >> 1) * 32;
    const int n0   = (wid & 1) * 64;

    const int rg = blockIdx.x, v = blockIdx.y, b = blockIdx.z;
    const int var = get_var(in_vars, v);

    const float* xbase = x + (size_t)(b * 8 + v) * (512 * 512) + (size_t)rg * 64 * 512;
    const float* wbase = w + (size_t)var * (128 * 256);

    if (tid < 128) smf[BIAS_OFF + tid] = bias[var * 128 + tid];

    float4 stA[8], stB[8];

    // ---- stage chunk 0 ----
    #pragma unroll
    for (int i = 0; i < 8; i++) {
        int idx = tid + 256 * i;            // A: 2048 float4s
        int rl = idx >> 7, c4 = idx & 127;
        int pr = rl >> 2, dp = rl & 3;
        stA[i] = *reinterpret_cast<const float4*>(
            xbase + (size_t)(pr * 16 + dp) * 512 + c4 * 4);
    }
    #pragma unroll
    for (int i = 0; i < 8; i++) {
        int idx = tid + 256 * i;            // B: 2048 float4s
        int e = idx >> 4, k4 = idx & 15;
        stB[i] = *reinterpret_cast<const float4*>(wbase + (size_t)e * 256 + k4 * 4);
    }
    // store chunk 0 -> buf 0 (convert to tf32)
    {
        float* As = smf + A_OFF;
        float* Bs = smf + B_OFF;
        #pragma unroll
        for (int i = 0; i < 8; i++) {
            int idx = tid + 256 * i;
            int rl = idx >> 7, c4 = idx & 127;
            int pr = rl >> 2, dp = rl & 3;
            int m = pr * 32 + (c4 >> 2);
            int k = dp * 16 + (c4 & 3) * 4;
            *reinterpret_cast<uint4*>(As + m * 68 + k) = cvt4(stA[i]);
        }
        #pragma unroll
        for (int i = 0; i < 8; i++) {
            int idx = tid + 256 * i;
            int e = idx >> 4, k4 = idx & 15;
            *reinterpret_cast<uint4*>(Bs + e * 68 + k4 * 4) = cvt4(stB[i]);
        }
    }
    __syncthreads();

    float acc[2][8][4];
    #pragma unroll
    for (int mf = 0; mf < 2; mf++)
        #pragma unroll
        for (int nf = 0; nf < 8; nf++)
            #pragma unroll
            for (int j = 0; j < 4; j++) acc[mf][nf][j] = 0.0f;

    #pragma unroll
    for (int c = 0; c < 4; c++) {
        // ---- prefetch chunk c+1 into registers ----
        if (c < 3) {
            #pragma unroll
            for (int i = 0; i < 8; i++) {
                int idx = tid + 256 * i;
                int rl = idx >> 7, c4 = idx & 127;
                int pr = rl >> 2, dp = rl & 3;
                stA[i] = *reinterpret_cast<const float4*>(
                    xbase + (size_t)(pr * 16 + (c + 1) * 4 + dp) * 512 + c4 * 4);
            }
            #pragma unroll
            for (int i = 0; i < 8; i++) {
                int idx = tid + 256 * i;
                int e = idx >> 4, k4 = idx & 15;
                stB[i] = *reinterpret_cast<const float4*>(
                    wbase + (size_t)e * 256 + (c + 1) * 64 + k4 * 4);
            }
        }

        // ---- compute chunk c from buffer c&1 ----
        {
            const float* As = smf + A_OFF + (c & 1) * 8704;
            const float* Bs = smf + B_OFF + (c & 1) * 8704;
            #pragma unroll
            for (int ks = 0; ks < 8; ks++) {
                const int k0 = ks * 8;
                uint32_t a[2][4];
                #pragma unroll
                for (int mf = 0; mf < 2; mf++) {
                    const float* ap = As + (m0 + mf * 16 + qrow) * 68 + k0 + qcol;
                    a[mf][0] = __float_as_uint(ap[0]);
                    a[mf][1] = __float_as_uint(ap[8 * 68]);
                    a[mf][2] = __float_as_uint(ap[4]);
                    a[mf][3] = __float_as_uint(ap[8 * 68 + 4]);
                }
                #pragma unroll
                for (int nf = 0; nf < 8; nf++) {
                    const float* bp = Bs + (n0 + nf * 8 + qrow) * 68 + k0 + qcol;
                    uint32_t b0 = __float_as_uint(bp[0]);
                    uint32_t b1 = __float_as_uint(bp[4]);
                    mma8(acc[0][nf], a[0], b0, b1);
                    mma8(acc[1][nf], a[1], b0, b1);
                }
            }
        }
        __syncthreads();

        // ---- store staged chunk c+1 into buffer (c+1)&1 ----
        if (c < 3) {
            float* As = smf + A_OFF + ((c + 1) & 1) * 8704;
            float* Bs = smf + B_OFF + ((c + 1) & 1) * 8704;
            #pragma unroll
            for (int i = 0; i < 8; i++) {
                int idx = tid + 256 * i;
                int rl = idx >> 7, c4 = idx & 127;
                int pr = rl >> 2, dp = rl & 3;
                int m = pr * 32 + (c4 >> 2);
                int k = dp * 16 + (c4 & 3) * 4;
                *reinterpret_cast<uint4*>(As + m * 68 + k) = cvt4(stA[i]);
            }
            #pragma unroll
            for (int i = 0; i < 8; i++) {
                int idx = tid + 256 * i;
                int e = idx >> 4, k4 = idx & 15;
                *reinterpret_cast<uint4*>(Bs + e * 68 + k4 * 4) = cvt4(stB[i]);
            }
            __syncthreads();
        }
    }

    // ---- epilogue: bias + store ----
    float* obase = out + (((size_t)(b * 8 + v) * 1024) + (size_t)rg * 128) * 128;
    const float* bs = smf + BIAS_OFF;
    #pragma unroll
    for (int mf = 0; mf < 2; mf++) {
        const int r = m0 + mf * 16 + qrow;
        #pragma unroll
        for (int nf = 0; nf < 8; nf++) {
            const int e0 = n0 + nf * 8 + qcol * 2;
            float2 lo, hi;
            lo.x = acc[mf][nf][0] + bs[e0];
            lo.y = acc[mf][nf][1] + bs[e0 + 1];
            hi.x = acc[mf][nf][2] + bs[e0];
            hi.y = acc[mf][nf][3] + bs[e0 + 1];
            *reinterpret_cast<float2*>(obase + (size_t)r * 128 + e0)       = lo;
            *reinterpret_cast<float2*>(obase + (size_t)(r + 8) * 128 + e0) = hi;
        }
    }
}

extern "C" void kernel_launch(void* const* d_in, const int* in_sizes, int n_in,
                              void* d_out, int out_size)
{
    const float* x       = (const float*)d_in[0];
    const int*   in_vars = (const int*)d_in[1];
    const float* w       = (const float*)d_in[2];
    const float* bias    = (const float*)d_in[3];
    float*       out     = (float*)d_out;

    cudaFuncSetAttribute(pve_mma_kernel,
                         cudaFuncAttributeMaxDynamicSharedMemorySize, SMEM_BYTES);

    dim3 grid(8, 8, 16);   // (row group, V, B) -> 1024 CTAs
    pve_mma_kernel<<<grid, THREADS, SMEM_BYTES>>>(x, in_vars, w, bias, out);
}